// round 4
// baseline (speedup 1.0000x reference)
#include <cuda_runtime.h>

// gnn_42460046688469 — Fourier-graph gather + complex weighted aggregate + permuted scatter.
//
// Interface handling is self-calibrating (content-based detection, all probe
// reads provably in-bounds). NEW this round: the OUTPUT layout is derived from
// out_size. The reference returns complex64, but the harness dtype set is
// {float32,int32,bf16}; if the conversion took the real part, out_size is
// (N+H)*C floats (67 MB), not (N+H)*C*2 (134 MB). All previous rounds wrote
// 134 MB unconditionally -> illegal access. Now:
//     out_size >= NH*32  -> interleaved (re,im) float pairs (complex view)
//     else               -> real part only, 16 floats per row
// and EVERY store is bounded by out_size floats.

#define K_NB 8

struct Cfg { int u; int is64; int niSel; int imagFirst; };
__device__ Cfg g_cfg;

__global__ void detect_kernel(const unsigned* __restrict__ m0,
                              const unsigned* __restrict__ m1,
                              const unsigned* __restrict__ m2,
                              const unsigned* __restrict__ hind,
                              int s_mid, int s_hi)
{
    if (threadIdx.x != 0 || blockIdx.x != 0) return;

    int Wm = s_mid >> 2;   // words provably in-bounds under both unit schemes
    int Wh = s_hi >> 2;

    const unsigned* ms[3] = { m0, m1, m2 };
    int isInt[3];
    {
        int step = Wm / 67; if (step < 1) step = 1;
        for (int b = 0; b < 3; ++b) {
            int ok = 1;
            for (int j = 0; j < 64; ++j) {
                unsigned v = ms[b][(j * step + j) % Wm];
                if (v >= 0x01000000u) { ok = 0; break; }
            }
            isInt[b] = ok;
        }
    }
    int niSel = 2;
    if (isInt[0] && !isInt[2]) niSel = 0;
    else if (isInt[1] && !isInt[0] && !isInt[2]) niSel = 1;
    int imagFirst = (niSel == 0) ? 1 : 0;

    int zeros = 0;
    {
        int step = Wh / 67; if (step < 1) step = 1;
        for (int j = 0; j < 64; ++j) {
            int w = ((j * step + j) % Wh) | 1;
            if (hind[w] == 0u) zeros++;
        }
    }
    int is64 = (zeros >= 48) ? 1 : 0;

    unsigned vmax = 0;
    {
        int step = Wh / 67; if (step < 1) step = 1;
        for (int j = 0; j < 64; ++j) {
            int w = (j * step + j) % Wh;
            if (is64) w &= ~1;
            unsigned v = hind[w];
            if (v > vmax) vmax = v;
        }
    }
    unsigned thresh = is64 ? (unsigned)(s_hi >> 3) : (unsigned)(s_hi >> 2);
    int u = (vmax >= thresh) ? 1 : 4;

    Cfg c; c.u = u; c.is64 = is64; c.niSel = niSel; c.imagFirst = imagFirst;
    g_cfg = c;
}

__device__ __forceinline__ int load_idx(const void* p, int off, int is64) {
    return is64 ? (int)((const long long*)p)[off] : ((const int*)p)[off];
}

__global__ void __launch_bounds__(256, 8) gnn_fourier_kernel(
    const float* __restrict__ xf0, const float* __restrict__ xf1,
    const void*  __restrict__ m0,  const void*  __restrict__ m1,
    const void*  __restrict__ m2,
    const void*  __restrict__ hmask, const void* __restrict__ hind,
    float4* __restrict__ out,
    int s_max, int s_mid, int s_hi, int s_hm, int out_count)
{
    Cfg c = g_cfg;

    int idxDiv = c.u * ((c.is64 && c.u == 4) ? 2 : 1);
    int NH     = s_hi / idxDiv;
    int H      = s_hm / idxDiv;
    int N      = (s_mid / c.u) / K_NB;
    int Mrows  = (s_max / c.u) / 16;

    int gid = blockIdx.x * blockDim.x + threadIdx.x;
    int row = gid >> 2;
    if (row >= NH) return;
    int t = gid & 3;

    const void* mids[3] = { m0, m1, m2 };
    const void* NIp = mids[c.niSel];
    const void* wa  = (c.niSel == 0) ? m1 : m0;
    const void* wb  = (c.niSel == 2) ? m1 : m2;
    const float* wR = (const float*)(c.imagFirst ? wb : wa);
    const float* wI = (const float*)(c.imagFirst ? wa : wb);
    const float4* XfR = (const float4*)(c.imagFirst ? xf1 : xf0);
    const float4* XfI = (const float4*)(c.imagFirst ? xf0 : xf1);

    unsigned src = (unsigned)load_idx(hind, row, c.is64);
    src = min(src, (unsigned)(NH - 1));

    float4 aR, aI;

    if ((int)src < N) {
        aR = make_float4(0.f, 0.f, 0.f, 0.f);
        aI = make_float4(0.f, 0.f, 0.f, 0.f);
        #pragma unroll
        for (int k = 0; k < K_NB; ++k) {
            int off = k * N + (int)src;
            unsigned idx = (unsigned)load_idx(NIp, off, c.is64);
            idx = min(idx, (unsigned)(Mrows - 1));
            float wr = __ldg(wR + off);
            float wi = __ldg(wI + off);
            float4 xr = __ldg(XfR + (long long)idx * 4 + t);
            float4 xi = __ldg(XfI + (long long)idx * 4 + t);
            aR.x = fmaf(wr, xr.x, fmaf(-wi, xi.x, aR.x));
            aR.y = fmaf(wr, xr.y, fmaf(-wi, xi.y, aR.y));
            aR.z = fmaf(wr, xr.z, fmaf(-wi, xi.z, aR.z));
            aR.w = fmaf(wr, xr.w, fmaf(-wi, xi.w, aR.w));
            aI.x = fmaf(wr, xi.x, fmaf(wi, xr.x, aI.x));
            aI.y = fmaf(wr, xi.y, fmaf(wi, xr.y, aI.y));
            aI.z = fmaf(wr, xi.z, fmaf(wi, xr.z, aI.z));
            aI.w = fmaf(wr, xi.w, fmaf(wi, xr.w, aI.w));
        }
    } else {
        unsigned hoff = min((unsigned)((int)src - N), (unsigned)(H - 1));
        unsigned idx = (unsigned)load_idx(hmask, (int)hoff, c.is64);
        idx = min(idx, (unsigned)(Mrows - 1));
        aR = __ldg(XfR + (long long)idx * 4 + t);
        aI = __ldg(XfI + (long long)idx * 4 + t);
    }

    // ---- output: layout chosen by out_size; every store bounded ----
    long long needF = (long long)NH * 32;     // floats for interleaved complex
    int maxF4 = out_count >> 2;               // out_count floats -> float4 bound

    if ((long long)out_count >= needF) {
        // interleaved (re,im) complex view: 8 float4 per row
        float4 o0 = make_float4(aR.x, aI.x, aR.y, aI.y);
        float4 o1 = make_float4(aR.z, aI.z, aR.w, aI.w);
        int ob = row * 8 + t * 2;
        if (ob + 1 < maxF4) {
            out[ob]     = o0;
            out[ob + 1] = o1;
        }
    } else {
        // real part only: 4 float4 per row
        int ob = row * 4 + t;
        if (ob < maxF4) out[ob] = aR;
    }
}

extern "C" void kernel_launch(void* const* d_in, const int* in_sizes, int n_in,
                              void* d_out, int out_size) {
    int smax = 0;
    for (int i = 0; i < n_in; ++i) if (in_sizes[i] > smax) smax = in_sizes[i];

    int smid = 0;
    for (int i = 0; i < n_in && !smid; ++i) {
        int s = in_sizes[i];
        if (s == smax || s <= 64) continue;
        int cnt = 0;
        for (int j = 0; j < n_in; ++j) if (in_sizes[j] == s) cnt++;
        if (cnt == 3) smid = s;
    }

    const float* xf[2] = { 0, 0 }; int nx = 0;
    const void*  mid[3] = { 0, 0, 0 }; int nm = 0;
    int hiPos = -1, hmPos = -1;
    if (smid) {
        for (int i = 0; i < n_in; ++i) {
            int s = in_sizes[i];
            if (s == smax)      { if (nx < 2) xf[nx++] = (const float*)d_in[i]; }
            else if (s == smid) { if (nm < 3) mid[nm++] = d_in[i]; }
            else if (s > 64) {
                if (hiPos < 0) hiPos = i;
                else if (s > in_sizes[hiPos]) { hmPos = hiPos; hiPos = i; }
                else hmPos = i;
            }
        }
    } else {
        int s2 = 0;
        for (int i = 0; i < n_in && !s2; ++i) {
            int s = in_sizes[i];
            if (s == smax || s <= 64) continue;
            int cnt = 0;
            for (int j = 0; j < n_in; ++j) if (in_sizes[j] == s) cnt++;
            if (cnt == 2) s2 = s;
        }
        smid = s2;
        int niPos = -1;
        for (int i = 0; i < n_in; ++i) if (in_sizes[i] == 2 * s2) niPos = i;
        int order[3], no = 0;
        for (int i = 0; i < n_in && no < 3; ++i)
            if (in_sizes[i] == s2 || i == niPos) order[no++] = i;
        for (int q = 0; q < 3; ++q) mid[q] = d_in[order[q]];
        for (int i = 0; i < n_in; ++i) {
            int s = in_sizes[i];
            if (s == smax) { if (nx < 2) xf[nx++] = (const float*)d_in[i]; }
            else if (s > 64 && s != s2 && i != niPos) {
                if (hiPos < 0) hiPos = i;
                else if (s > in_sizes[hiPos]) { hmPos = hiPos; hiPos = i; }
                else hmPos = i;
            }
        }
    }

    int s_hi = in_sizes[hiPos];
    int s_hm = in_sizes[hmPos];

    detect_kernel<<<1, 32>>>((const unsigned*)mid[0], (const unsigned*)mid[1],
                             (const unsigned*)mid[2], (const unsigned*)d_in[hiPos],
                             smid, s_hi);

    long long rows_max = s_hi;   // worst case; excess threads exit
    long long total_threads = rows_max * 4;
    int block = 256;
    long long grid = (total_threads + block - 1) / block;

    gnn_fourier_kernel<<<(int)grid, block>>>(xf[0], xf[1], mid[0], mid[1], mid[2],
                                             d_in[hmPos], d_in[hiPos],
                                             (float4*)d_out,
                                             smax, smid, s_hi, s_hm, out_size);
}